// round 3
// baseline (speedup 1.0000x reference)
#include <cuda_runtime.h>
#include <math.h>
#include <stdint.h>

// Problem constants
#define Bn   32
#define NIc  2048
#define NOc  128
#define TIc  128             // i's per block
#define NTc  (NIc / TIc)     // 16 tiles
#define RW   36              // padded row width (floats) of g_part: [0]=S0, [4..19]=S1, [20..35]=S2
#define EPSf 1e-9f
#define LOG2PIf 1.8378770664093453f

#define LAM1 0.0005f         // 0.01*(1-0.95)
#define LAM2 0.000975f       // 0.01*(1-0.95^2)
#define LAM3 0.00142625f     // 0.01*(1-0.95^3)

// Deterministic two-stage reduction scratch (module-static: allocation-free)
__device__ __align__(16) float g_part[(size_t)Bn * NTc * NOc * RW];
// g_stats[b][j][33]: [0..15]=mu, [16..31]=1/sigma2, [32]=L = log(a_out+eps)-0.5*logsum-8*log2pi
__device__ __align__(16) float g_stats[(size_t)Bn * NOc * 33];

// ---------------- f32x2 packed helpers (Blackwell fma.rn.f32x2) ----------------
__device__ __forceinline__ uint64_t pk2(float lo, float hi) {
    uint64_t r; asm("mov.b64 %0, {%1, %2};" : "=l"(r) : "f"(lo), "f"(hi)); return r;
}
__device__ __forceinline__ void upk2(uint64_t v, float& lo, float& hi) {
    asm("mov.b64 {%0, %1}, %2;" : "=f"(lo), "=f"(hi) : "l"(v));
}
__device__ __forceinline__ uint64_t fma2(uint64_t a, uint64_t b, uint64_t c) {
    uint64_t d; asm("fma.rn.f32x2 %0, %1, %2, %3;" : "=l"(d) : "l"(a), "l"(b), "l"(c)); return d;
}
__device__ __forceinline__ uint64_t mul2(uint64_t a, uint64_t b) {
    uint64_t d; asm("mul.rn.f32x2 %0, %1, %2;" : "=l"(d) : "l"(a), "l"(b)); return d;
}
__device__ __forceinline__ uint64_t add2(uint64_t a, uint64_t b) {
    uint64_t d; asm("add.rn.f32x2 %0, %1, %2;" : "=l"(d) : "l"(a), "l"(b)); return d;
}

// ============================================================================
// Pass kernel. Block = 512 threads covering TWO b's (halves) for one i-tile.
// Per half: thread tt owns j = tt>>1 and 8 d's (h = tt&1 selects d-half), all
// math packed as f32x2 over d-pairs. Votes recomputed from W (L2) + pose
// (uniform b64 loads). Non-uniform passes rebuild R via logp + softmax with
// 2 block barriers per i (max exchange, sum exchange); logits never touch smem.
// Accumulates S0/S1/S2 partials to g_part (b64 stores).
// ============================================================================
template <bool UNIFORM>
__global__ __launch_bounds__(512, 1) void pass_kernel(
    const float* __restrict__ pose,   // [B, NI, 4, 4]
    const float* __restrict__ act,    // [B, NI]
    const float* __restrict__ W)      // [NI, NO, 4, 4]
{
    __shared__ float sAct[2][TIc];
    __shared__ float sM[2][8];
    __shared__ float sS[2][8];

    const int t    = threadIdx.x;
    const int half = t >> 8;          // which b of the pair
    const int tt   = t & 255;
    const int j    = tt >> 1;
    const int h    = tt & 1;
    const int d0   = h << 3;
    const int lane = t & 31;
    const int wh   = (t >> 5) & 7;    // warp index within half
    const int tile = blockIdx.x;
    const int b    = (blockIdx.y << 1) + half;
    const int i0   = tile * TIc;

    // persistent per-thread stats for this (b, j, d0..d0+7), packed
    uint64_t negmu[4], invs[4];
    float sLj = 0.f;
    if (!UNIFORM) {
        const float* st = g_stats + (size_t)(b * NOc + j) * 33;
        #pragma unroll
        for (int pi = 0; pi < 4; pi++) {
            negmu[pi] = pk2(-st[d0 + 2 * pi], -st[d0 + 2 * pi + 1]);
            invs[pi]  = pk2(st[16 + d0 + 2 * pi], st[16 + d0 + 2 * pi + 1]);
        }
        sLj = st[32];
    }
    if (tt < TIc) sAct[half][tt] = act[b * NIc + i0 + tt];
    __syncthreads();

    uint64_t a1p[4] = {0, 0, 0, 0}, a2p[4] = {0, 0, 0, 0};
    float s0 = 0.f;

    #pragma unroll 1
    for (int ii = 0; ii < TIc; ii++) {
        const int i = i0 + ii;

        // pose pairs (q, q+1) loaded directly as b64 (uniform address per half)
        const uint64_t* p64 = (const uint64_t*)(pose + ((size_t)b * NIc + i) * 16);
        uint64_t ppk[8];
        #pragma unroll
        for (int r8 = 0; r8 < 8; r8++) ppk[r8] = p64[r8];  // ppk[r*2+qq]

        // W rows p = 2h, 2h+1 for this j
        const float4* wrow = (const float4*)(W + ((size_t)i * NOc + j) * 16 + (h << 3));
        const float4 w0 = wrow[0];
        const float4 w1 = wrow[1];

        // votes, packed over q-pairs: vp[pi] = (v[d0+2pi], v[d0+2pi+1])
        uint64_t vp[4];
        {
            const uint64_t wa0 = pk2(w0.x, w0.x), wa1 = pk2(w0.y, w0.y),
                           wa2 = pk2(w0.z, w0.z), wa3 = pk2(w0.w, w0.w);
            const uint64_t wb0 = pk2(w1.x, w1.x), wb1 = pk2(w1.y, w1.y),
                           wb2 = pk2(w1.z, w1.z), wb3 = pk2(w1.w, w1.w);
            #pragma unroll
            for (int qq = 0; qq < 2; qq++) {
                vp[qq]     = fma2(wa0, ppk[0 + qq], fma2(wa1, ppk[2 + qq],
                             fma2(wa2, ppk[4 + qq], mul2(wa3, ppk[6 + qq]))));
                vp[2 + qq] = fma2(wb0, ppk[0 + qq], fma2(wb1, ppk[2 + qq],
                             fma2(wb2, ppk[4 + qq], mul2(wb3, ppk[6 + qq]))));
            }
        }

        float rp;
        if (UNIFORM) {
            rp = sAct[half][ii] * (1.f / NOc);
        } else {
            // logp quadratic term (packed), then combine d-halves via xor-1
            uint64_t q2 = 0;
            #pragma unroll
            for (int pi = 0; pi < 4; pi++) {
                const uint64_t df = add2(vp[pi], negmu[pi]);
                q2 = fma2(mul2(df, df), invs[pi], q2);
            }
            float qlo, qhi; upk2(q2, qlo, qhi);
            float qs = qlo + qhi;
            qs += __shfl_xor_sync(0xffffffffu, qs, 1);
            const float x = fmaf(-0.5f, qs, sLj);

            // warp max over the 16 distinct j's (offsets 16..2: each j once,
            // both h-lanes converge to the same value)
            float m = x;
            #pragma unroll
            for (int off = 16; off > 1; off >>= 1)
                m = fmaxf(m, __shfl_xor_sync(0xffffffffu, m, off));
            if (lane == 0) sM[half][wh] = m;
            __syncthreads();
            float M = sM[half][0];
            #pragma unroll
            for (int k = 1; k < 8; k++) M = fmaxf(M, sM[half][k]);

            const float e = __expf(x - M);
            float s = e;
            #pragma unroll
            for (int off = 16; off > 1; off >>= 1)
                s += __shfl_xor_sync(0xffffffffu, s, off);
            if (lane == 0) sS[half][wh] = s;
            __syncthreads();
            float T = sS[half][0];
            #pragma unroll
            for (int k = 1; k < 8; k++) T += sS[half][k];

            rp = e * __fdividef(sAct[half][ii], T);   // R_new * a_in
        }

        if (!h) s0 += rp;
        const uint64_t rpp = pk2(rp, rp);
        #pragma unroll
        for (int pi = 0; pi < 4; pi++) {
            a1p[pi] = fma2(rpp, vp[pi], a1p[pi]);
            a2p[pi] = fma2(mul2(rpp, vp[pi]), vp[pi], a2p[pi]);
        }
    }

    // write block partials: row [S0, pad, pad, pad, S1[0..15], S2[0..15]]
    float* pb = g_part + ((size_t)(b * NTc + tile) * NOc + j) * RW;
    if (!h) pb[0] = s0;
    #pragma unroll
    for (int pi = 0; pi < 4; pi++) {
        *(uint64_t*)(pb + 4  + d0 + 2 * pi) = a1p[pi];
        *(uint64_t*)(pb + 20 + d0 + 2 * pi) = a2p[pi];
    }
}

// ============================================================================
// Stats kernel: one warp per (b, j). Lane = stat index within the 36-float
// row; loop over NTc tiles with coalesced reads, reduce in-register, gather
// the per-d stats via shuffles, compute mu / sigma2 / a_out (+ next-pass L,
// 1/sigma2, or the final outputs).
// ============================================================================
template <bool FINAL>
__global__ __launch_bounds__(256) void stats_kernel(
    const float* __restrict__ beta_v,
    const float* __restrict__ beta_a,
    float lam,
    float* __restrict__ out)
{
    const int warp = (blockIdx.x * blockDim.x + threadIdx.x) >> 5;  // 0..4095
    const int lane = threadIdx.x & 31;
    const int b = warp >> 7;
    const int j = warp & 127;

    const float* base = g_part + ((size_t)b * NTc * NOc + j) * RW;
    float acc = 0.f;    // stat index = lane (0..31)
    float acc2 = 0.f;   // lanes 0..3 also carry stat 32+lane
    #pragma unroll
    for (int tile = 0; tile < NTc; tile++) {
        const float* row = base + (size_t)tile * (NOc * RW);
        acc += row[lane];
        if (lane < 4) acc2 += row[32 + lane];
    }

    const int d = lane & 15;
    const float S0  = __shfl_sync(0xffffffffu, acc, 0);
    const float S1d = __shfl_sync(0xffffffffu, acc, 4 + d);
    const float s2a = __shfl_sync(0xffffffffu, acc, (20 + d) & 31);
    const float s2b = __shfl_sync(0xffffffffu, acc2, (d >= 12) ? (d - 12) : 0);
    const float S2d = (d < 12) ? s2a : s2b;

    const float Rs = S0 + EPSf;
    const float invRs = 1.f / Rs;
    const float muv = S1d * invRs;
    // sum Rp*(v-mu)^2 = S2 - 2*mu*S1 + mu^2*S0 (exact expansion)
    const float srp = S2d - 2.f * muv * S1d + muv * muv * S0;
    const float sig = srp * invRs + EPSf;
    const float lg  = logf(sig);
    float logsum = lg;
    #pragma unroll
    for (int off = 8; off; off >>= 1)
        logsum += __shfl_xor_sync(0xffffffffu, logsum, off);

    const float cost = (16.f * beta_v[j] + 0.5f * logsum) * Rs;
    const float aout = 1.f / (1.f + expf(-(lam * (beta_a[j] - cost))));

    if (FINAL) {
        if (lane < 16) out[(size_t)(b * NOc + j) * 16 + d] = muv;        // pose_out
        if (lane == 0) out[(size_t)Bn * NOc * 16 + b * NOc + j] = aout;  // a_out
    } else {
        float* st = g_stats + (size_t)(b * NOc + j) * 33;
        if (lane < 16) {
            st[d]      = muv;
            st[16 + d] = 1.f / sig;
        }
        if (lane == 0)
            st[32] = logf(aout + EPSf) - 0.5f * logsum - 8.f * LOG2PIf;
    }
}

extern "C" void kernel_launch(void* const* d_in, const int* in_sizes, int n_in,
                              void* d_out, int out_size) {
    const float* pose   = (const float*)d_in[0];   // [32, 2048, 4, 4]
    const float* act    = (const float*)d_in[1];   // [32, 2048]
    const float* W      = (const float*)d_in[2];   // [2048, 128, 4, 4]
    const float* beta_v = (const float*)d_in[3];   // [128]
    const float* beta_a = (const float*)d_in[4];   // [128]
    float* out = (float*)d_out;                    // pose_out (65536) ++ a_out (4096)

    dim3 gp(NTc, Bn / 2);                     // 16 x 16 blocks, 512 threads (2 b's each)
    const int sgrid = (Bn * NOc * 32) / 256;  // 512 blocks, warp per (b,j)

    // t=0: uniform R
    pass_kernel<true><<<gp, 512>>>(pose, act, W);
    stats_kernel<false><<<sgrid, 256>>>(beta_v, beta_a, LAM1, out);
    // t=1: R from stats0, accumulate
    pass_kernel<false><<<gp, 512>>>(pose, act, W);
    stats_kernel<false><<<sgrid, 256>>>(beta_v, beta_a, LAM2, out);
    // t=2: R from stats1, accumulate; final stats write outputs
    pass_kernel<false><<<gp, 512>>>(pose, act, W);
    stats_kernel<true><<<sgrid, 256>>>(beta_v, beta_a, LAM3, out);
}

// round 4
// speedup vs baseline: 1.1096x; 1.1096x over previous
#include <cuda_runtime.h>
#include <math.h>
#include <stdint.h>

// Problem constants
#define Bn   32
#define NIc  2048
#define NOc  128
#define TIc  32              // i's per block
#define NTc  (NIc / TIc)     // 64 tiles
#define RW   36              // g_part row: [0]=S0, [4..19]=S1(permuted), [20..35]=S2(permuted)
#define EPSf 1e-9f
#define LOG2PIf 1.8378770664093453f

#define LAM1 0.0005f         // 0.01*(1-0.95)
#define LAM2 0.000975f       // 0.01*(1-0.95^2)
#define LAM3 0.00142625f     // 0.01*(1-0.95^3)

// Deterministic two-stage reduction scratch (module-static: allocation-free)
__device__ __align__(16) float g_part[(size_t)Bn * NTc * NOc * RW];
// Transposed stats: g_statsT[b][s][j], s: 0..15 = mu(d), 16..31 = 1/sigma2(d), 32 = L
__device__ __align__(16) float g_statsT[(size_t)Bn * 33 * NOc];

// ---------------- f32x2 packed helpers ----------------
static __device__ __forceinline__ uint64_t pk2(float lo, float hi) {
    uint64_t r; asm("mov.b64 %0, {%1, %2};" : "=l"(r) : "f"(lo), "f"(hi)); return r;
}
static __device__ __forceinline__ void upk2(uint64_t v, float& lo, float& hi) {
    asm("mov.b64 {%0, %1}, %2;" : "=f"(lo), "=f"(hi) : "l"(v));
}
static __device__ __forceinline__ uint64_t fma2(uint64_t a, uint64_t b, uint64_t c) {
    uint64_t d; asm("fma.rn.f32x2 %0, %1, %2, %3;" : "=l"(d) : "l"(a), "l"(b), "l"(c)); return d;
}
static __device__ __forceinline__ uint64_t mul2(uint64_t a, uint64_t b) {
    uint64_t d; asm("mul.rn.f32x2 %0, %1, %2;" : "=l"(d) : "l"(a), "l"(b)); return d;
}
static __device__ __forceinline__ uint64_t add2(uint64_t a, uint64_t b) {
    uint64_t d; asm("add.rn.f32x2 %0, %1, %2;" : "=l"(d) : "l"(a), "l"(b)); return d;
}

// ============================================================================
// Pass kernel. Block = 128 threads = 4 warps; thread t owns output capsule
// j = t (ALL 16 d's), for TWO b's (b0, b0+1) over one i-tile. W[i][j] is
// loaded once per i and shared by both b-streams. Packed f32x2 math over
// d-pairs (p,p+1) -> packed slot k = pp*4+q holds d = (8pp+q, 8pp+q+4).
// Softmax over j: warp butterfly (m,s) + ONE __syncthreads per i, slots
// parity-double-buffered. Uniform pass: no barriers in the loop at all.
// ============================================================================
template <bool UNIFORM>
__global__ __launch_bounds__(128) void pass_kernel(
    const float* __restrict__ pose,   // [B, NI, 4, 4]
    const float* __restrict__ act,    // [B, NI]
    const float* __restrict__ W)      // [NI, NO, 4, 4]
{
    __shared__ uint64_t sPoseD[2][TIc][16];  // dup-packed pose: (f,f)
    __shared__ float    sAct[2][TIc];
    __shared__ uint64_t sSlot[2][2][4];      // [parity][bb][warp] = (m_w, s_w)

    const int t    = threadIdx.x;
    const int j    = t;
    const int w    = t >> 5;
    const int tile = blockIdx.x;
    const int b0   = blockIdx.y << 1;
    const int i0   = tile * TIc;

    // stage dup-packed pose + act for both b's (coalesced reads)
    for (int idx = t; idx < 2 * TIc * 16; idx += 128) {
        const int bb  = idx >> 9;          // / (TIc*16)
        const int rem = idx & 511;
        const float f = pose[((size_t)(b0 + bb) * NIc + i0 + (rem >> 4)) * 16 + (rem & 15)];
        sPoseD[bb][rem >> 4][rem & 15] = pk2(f, f);
    }
    if (t < 2 * TIc)
        sAct[t >> 5][t & 31] = act[(b0 + (t >> 5)) * NIc + i0 + (t & 31)];

    // per-thread stats for (b, j): packed -mu, 1/sigma2 (coalesced via g_statsT)
    uint64_t negmu[2][8], invsv[2][8];
    float sL[2];
    if (!UNIFORM) {
        #pragma unroll
        for (int bb = 0; bb < 2; bb++) {
            const float* st = g_statsT + (size_t)(b0 + bb) * 33 * NOc;
            float muv[16], iv[16];
            #pragma unroll
            for (int d = 0; d < 16; d++) {
                muv[d] = st[d * NOc + j];
                iv[d]  = st[(16 + d) * NOc + j];
            }
            sL[bb] = st[32 * NOc + j];
            #pragma unroll
            for (int k = 0; k < 8; k++) {
                const int pp = k >> 2, q = k & 3;
                negmu[bb][k] = pk2(-muv[8 * pp + q], -muv[8 * pp + q + 4]);
                invsv[bb][k] = pk2(iv[8 * pp + q], iv[8 * pp + q + 4]);
            }
        }
    }
    __syncthreads();

    uint64_t S1[2][8], S2[2][8];
    float S0[2] = {0.f, 0.f};
    #pragma unroll
    for (int bb = 0; bb < 2; bb++)
        #pragma unroll
        for (int k = 0; k < 8; k++) { S1[bb][k] = 0ull; S2[bb][k] = 0ull; }

    #pragma unroll 1
    for (int ii = 0; ii < TIc; ii++) {
        const int par = ii & 1;
        // W[i][j]: 4 rows (float4), shared by both b's; pack (p,p+1) pairs
        const float4* wr = (const float4*)(W + ((size_t)(i0 + ii) * NOc + j) * 16);
        const float4 w0 = wr[0], w1 = wr[1], w2 = wr[2], w3 = wr[3];
        uint64_t wpk[8];
        wpk[0] = pk2(w0.x, w1.x); wpk[1] = pk2(w0.y, w1.y);
        wpk[2] = pk2(w0.z, w1.z); wpk[3] = pk2(w0.w, w1.w);
        wpk[4] = pk2(w2.x, w3.x); wpk[5] = pk2(w2.y, w3.y);
        wpk[6] = pk2(w2.z, w3.z); wpk[7] = pk2(w2.w, w3.w);

        uint64_t vp[2][8];
        float ee[2];
        #pragma unroll
        for (int bb = 0; bb < 2; bb++) {
            const uint64_t* pd = sPoseD[bb][ii];
            #pragma unroll
            for (int k = 0; k < 8; k++) {
                const int pp = k >> 2, q = k & 3;
                uint64_t a = mul2(wpk[pp * 4 + 0], pd[0 * 4 + q]);
                a = fma2(wpk[pp * 4 + 1], pd[1 * 4 + q], a);
                a = fma2(wpk[pp * 4 + 2], pd[2 * 4 + q], a);
                a = fma2(wpk[pp * 4 + 3], pd[3 * 4 + q], a);
                vp[bb][k] = a;   // (v[8pp+q], v[8pp+q+4])
            }
            if (!UNIFORM) {
                uint64_t q2 = 0ull;
                #pragma unroll
                for (int k = 0; k < 8; k++) {
                    const uint64_t df = add2(vp[bb][k], negmu[bb][k]);
                    q2 = fma2(mul2(df, df), invsv[bb][k], q2);
                }
                float ql, qh; upk2(q2, ql, qh);
                const float x = fmaf(-0.5f, ql + qh, sL[bb]);
                float m = x;
                #pragma unroll
                for (int off = 16; off; off >>= 1)
                    m = fmaxf(m, __shfl_xor_sync(0xffffffffu, m, off));
                const float e = __expf(x - m);
                float s = e;
                #pragma unroll
                for (int off = 16; off; off >>= 1)
                    s += __shfl_xor_sync(0xffffffffu, s, off);
                if ((t & 31) == 0) sSlot[par][bb][w] = pk2(m, s);
                ee[bb] = e;
            }
        }

        if (UNIFORM) {
            #pragma unroll
            for (int bb = 0; bb < 2; bb++) {
                const float rp = sAct[bb][ii] * (1.f / NOc);
                S0[bb] += rp;
                const uint64_t rpp = pk2(rp, rp);
                #pragma unroll
                for (int k = 0; k < 8; k++) {
                    const uint64_t tmp = mul2(rpp, vp[bb][k]);
                    S1[bb][k] = add2(S1[bb][k], tmp);
                    S2[bb][k] = fma2(tmp, vp[bb][k], S2[bb][k]);
                }
            }
        } else {
            __syncthreads();   // the ONLY barrier per i (covers both b's)
            #pragma unroll
            for (int bb = 0; bb < 2; bb++) {
                float m0, sA, m1, sB, m2, sC, m3, sD;
                upk2(sSlot[par][bb][0], m0, sA);
                upk2(sSlot[par][bb][1], m1, sB);
                upk2(sSlot[par][bb][2], m2, sC);
                upk2(sSlot[par][bb][3], m3, sD);
                const float M = fmaxf(fmaxf(m0, m1), fmaxf(m2, m3));
                const float f0 = __expf(m0 - M), f1 = __expf(m1 - M);
                const float f2 = __expf(m2 - M), f3 = __expf(m3 - M);
                const float T = sA * f0 + sB * f1 + sC * f2 + sD * f3;
                const float fw = (w == 0) ? f0 : (w == 1) ? f1 : (w == 2) ? f2 : f3;
                const float rp = ee[bb] * fw * __fdividef(sAct[bb][ii], T);
                S0[bb] += rp;
                const uint64_t rpp = pk2(rp, rp);
                #pragma unroll
                for (int k = 0; k < 8; k++) {
                    const uint64_t tmp = mul2(rpp, vp[bb][k]);
                    S1[bb][k] = add2(S1[bb][k], tmp);
                    S2[bb][k] = fma2(tmp, vp[bb][k], S2[bb][k]);
                }
            }
        }
    }

    #pragma unroll
    for (int bb = 0; bb < 2; bb++) {
        float* pb = g_part + ((size_t)((b0 + bb) * NTc + tile) * NOc + j) * RW;
        pb[0] = S0[bb];
        #pragma unroll
        for (int k = 0; k < 8; k++) {
            *(uint64_t*)(pb + 4  + 2 * k) = S1[bb][k];   // (d=8pp+q, d=8pp+q+4)
            *(uint64_t*)(pb + 20 + 2 * k) = S2[bb][k];
        }
    }
}

// ============================================================================
// Stats kernel: one warp per (b, j); lane = stat slot. Coalesced tile loop,
// in-register reduce, shuffle-gather with the (p,p+1)-pair permutation undone,
// then mu / sigma2 / a_out (+ next-pass L & 1/sigma2 into g_statsT, or the
// final outputs).
// ============================================================================
template <bool FINAL>
__global__ __launch_bounds__(256) void stats_kernel(
    const float* __restrict__ beta_v,
    const float* __restrict__ beta_a,
    float lam,
    float* __restrict__ out)
{
    const int warp = (blockIdx.x * blockDim.x + threadIdx.x) >> 5;  // 0..4095
    const int lane = threadIdx.x & 31;
    const int b = warp >> 7;
    const int j = warp & 127;

    const float* base = g_part + ((size_t)b * NTc * NOc + j) * RW;
    float acc = 0.f;    // stat slot = lane (0..31)
    float acc2 = 0.f;   // lanes 0..3 carry slots 32..35
    #pragma unroll 4
    for (int tile = 0; tile < NTc; tile++) {
        const float* row = base + (size_t)tile * (NOc * RW);
        acc += row[lane];
        if (lane < 4) acc2 += row[32 + lane];
    }

    const int d  = lane & 15;
    const int q  = d & 3, pp = (d >> 3) & 1, h = (d >> 2) & 1;
    const int sl = 8 * pp + 2 * q + h;   // permuted slot of d, 0..15
    const float S0  = __shfl_sync(0xffffffffu, acc, 0);
    const float S1d = __shfl_sync(0xffffffffu, acc, 4 + sl);
    const float s2a = __shfl_sync(0xffffffffu, acc, (20 + sl) & 31);
    const float s2b = __shfl_sync(0xffffffffu, acc2, (sl >= 12) ? (sl - 12) : 0);
    const float S2d = (sl < 12) ? s2a : s2b;

    const float Rs = S0 + EPSf;
    const float invRs = 1.f / Rs;
    const float muv = S1d * invRs;
    // sum Rp*(v-mu)^2 = S2 - 2*mu*S1 + mu^2*S0 (exact expansion)
    const float srp = S2d - 2.f * muv * S1d + muv * muv * S0;
    const float sig = srp * invRs + EPSf;
    const float lg  = logf(sig);
    float logsum = lg;
    #pragma unroll
    for (int off = 8; off; off >>= 1)
        logsum += __shfl_xor_sync(0xffffffffu, logsum, off);

    const float cost = (16.f * beta_v[j] + 0.5f * logsum) * Rs;
    const float aout = 1.f / (1.f + expf(-(lam * (beta_a[j] - cost))));

    if (FINAL) {
        if (lane < 16) out[(size_t)(b * NOc + j) * 16 + d] = muv;        // pose_out
        if (lane == 0) out[(size_t)Bn * NOc * 16 + b * NOc + j] = aout;  // a_out
    } else {
        float* st = g_statsT + (size_t)b * 33 * NOc;
        if (lane < 16) {
            st[d * NOc + j]        = muv;
            st[(16 + d) * NOc + j] = 1.f / sig;
        }
        if (lane == 0)
            st[32 * NOc + j] = logf(aout + EPSf) - 0.5f * logsum - 8.f * LOG2PIf;
    }
}

extern "C" void kernel_launch(void* const* d_in, const int* in_sizes, int n_in,
                              void* d_out, int out_size) {
    const float* pose   = (const float*)d_in[0];   // [32, 2048, 4, 4]
    const float* act    = (const float*)d_in[1];   // [32, 2048]
    const float* W      = (const float*)d_in[2];   // [2048, 128, 4, 4]
    const float* beta_v = (const float*)d_in[3];   // [128]
    const float* beta_a = (const float*)d_in[4];   // [128]
    float* out = (float*)d_out;                    // pose_out (65536) ++ a_out (4096)

    dim3 gp(NTc, Bn / 2);                     // 64 x 16 blocks, 128 threads (2 b's each)
    const int sgrid = (Bn * NOc * 32) / 256;  // 512 blocks, warp per (b,j)

    // t=0: uniform R
    pass_kernel<true><<<gp, 128>>>(pose, act, W);
    stats_kernel<false><<<sgrid, 256>>>(beta_v, beta_a, LAM1, out);
    // t=1: R from stats0, accumulate
    pass_kernel<false><<<gp, 128>>>(pose, act, W);
    stats_kernel<false><<<sgrid, 256>>>(beta_v, beta_a, LAM2, out);
    // t=2: R from stats1, accumulate; final stats write outputs
    pass_kernel<false><<<gp, 128>>>(pose, act, W);
    stats_kernel<true><<<sgrid, 256>>>(beta_v, beta_a, LAM3, out);
}

// round 6
// speedup vs baseline: 1.3012x; 1.1727x over previous
#include <cuda_runtime.h>
#include <math.h>
#include <stdint.h>

// Problem constants
#define Bn   32
#define NIc  2048
#define NOc  128
#define TIc  64              // i's per block in pass kernels
#define NTc  (NIc / TIc)     // 32 tiles
#define RW   36              // g_part row: [0]=S0, [4..19]=S1(permuted), [20..35]=S2(permuted)
#define EPSf 1e-9f
#define LOG2PIf 1.8378770664093453f

#define LAM1 0.0005f         // 0.01*(1-0.95)
#define LAM2 0.000975f       // 0.01*(1-0.95^2)
#define LAM3 0.00142625f     // 0.01*(1-0.95^3)

// Module-static scratch (allocation-free, deterministic)
__device__ __align__(16) float g_part[(size_t)Bn * NTc * NOc * RW];   // 18.9 MB
__device__ __align__(16) float g_statsT[(size_t)Bn * 33 * NOc];       // [b][s][j]
__device__ __align__(16) float g_x[(size_t)Bn * NIc * NOc];           // logits, 33.5 MB
__device__ __align__(16) float2 g_rowMT[(size_t)Bn * NIc];            // (M, a/T) per row

// ---------------- f32x2 packed helpers ----------------
static __device__ __forceinline__ uint64_t pk2(float lo, float hi) {
    uint64_t r; asm("mov.b64 %0, {%1, %2};" : "=l"(r) : "f"(lo), "f"(hi)); return r;
}
static __device__ __forceinline__ void upk2(uint64_t v, float& lo, float& hi) {
    asm("mov.b64 {%0, %1}, %2;" : "=f"(lo), "=f"(hi) : "l"(v));
}
static __device__ __forceinline__ uint64_t fma2(uint64_t a, uint64_t b, uint64_t c) {
    uint64_t d; asm("fma.rn.f32x2 %0, %1, %2, %3;" : "=l"(d) : "l"(a), "l"(b), "l"(c)); return d;
}
static __device__ __forceinline__ uint64_t mul2(uint64_t a, uint64_t b) {
    uint64_t d; asm("mul.rn.f32x2 %0, %1, %2;" : "=l"(d) : "l"(a), "l"(b)); return d;
}
static __device__ __forceinline__ uint64_t add2(uint64_t a, uint64_t b) {
    uint64_t d; asm("add.rn.f32x2 %0, %1, %2;" : "=l"(d) : "l"(a), "l"(b)); return d;
}

// Compute the 8 packed vote slots for one (i, j): slot k=(pp*4+q) holds
// (v[8pp+q], v[8pp+q+4]). wpk[pp*4+r] = (W[2pp][r], W[2pp+1][r]); pd = dup-
// packed pose (pd[4r+q] = (pose[r][q], pose[r][q])).
static __device__ __forceinline__ void votes8(const uint64_t* __restrict__ wpk,
                                              const uint64_t* __restrict__ pd,
                                              uint64_t* __restrict__ vp) {
    #pragma unroll
    for (int k = 0; k < 8; k++) {
        const int pp = k >> 2, q = k & 3;
        uint64_t a = mul2(wpk[pp * 4 + 0], pd[0 + q]);
        a = fma2(wpk[pp * 4 + 1], pd[4 + q], a);
        a = fma2(wpk[pp * 4 + 2], pd[8 + q], a);
        vp[k] = fma2(wpk[pp * 4 + 3], pd[12 + q], a);
    }
}

static __device__ __forceinline__ void loadW8(const float* __restrict__ W,
                                              int i, int j, uint64_t* wpk) {
    const float4* wr = (const float4*)(W + ((size_t)i * NOc + j) * 16);
    const float4 w0 = wr[0], w1 = wr[1], w2 = wr[2], w3 = wr[3];
    wpk[0] = pk2(w0.x, w1.x); wpk[1] = pk2(w0.y, w1.y);
    wpk[2] = pk2(w0.z, w1.z); wpk[3] = pk2(w0.w, w1.w);
    wpk[4] = pk2(w2.x, w3.x); wpk[5] = pk2(w2.y, w3.y);
    wpk[6] = pk2(w2.z, w3.z); wpk[7] = pk2(w2.w, w3.w);
}

// ============================================================================
// K1: logit kernel. Block = 128 threads (j = tid), two b's, one i-tile.
// Recomputes votes, evaluates x = L - 0.5*sum_d (v-mu)^2/sigma2, streams x out.
// No barriers in the loop, no accumulators -> high occupancy, pure stream.
// ============================================================================
__global__ __launch_bounds__(128) void logit_kernel(
    const float* __restrict__ pose, const float* __restrict__ W)
{
    __shared__ uint64_t sPoseD[2][TIc][16];

    const int j    = threadIdx.x;
    const int tile = blockIdx.x;
    const int b0   = blockIdx.y << 1;
    const int i0   = tile * TIc;

    for (int idx = threadIdx.x; idx < 2 * TIc * 16; idx += 128) {
        const int bb = idx >> 10, rem = idx & 1023;
        const float f = pose[((size_t)(b0 + bb) * NIc + i0 + (rem >> 4)) * 16 + (rem & 15)];
        sPoseD[bb][rem >> 4][rem & 15] = pk2(f, f);
    }

    uint64_t negmu[2][8], invsv[2][8];
    float sL[2];
    #pragma unroll
    for (int bb = 0; bb < 2; bb++) {
        const float* st = g_statsT + (size_t)(b0 + bb) * 33 * NOc;
        float muv[16], iv[16];
        #pragma unroll
        for (int d = 0; d < 16; d++) {
            muv[d] = st[d * NOc + j];
            iv[d]  = st[(16 + d) * NOc + j];
        }
        sL[bb] = st[32 * NOc + j];
        #pragma unroll
        for (int k = 0; k < 8; k++) {
            const int pp = k >> 2, q = k & 3;
            negmu[bb][k] = pk2(-muv[8 * pp + q], -muv[8 * pp + q + 4]);
            invsv[bb][k] = pk2(iv[8 * pp + q], iv[8 * pp + q + 4]);
        }
    }
    __syncthreads();

    #pragma unroll 1
    for (int ii = 0; ii < TIc; ii++) {
        uint64_t wpk[8];
        loadW8(W, i0 + ii, j, wpk);
        #pragma unroll
        for (int bb = 0; bb < 2; bb++) {
            uint64_t vp[8];
            votes8(wpk, sPoseD[bb][ii], vp);
            uint64_t q2 = 0ull;
            #pragma unroll
            for (int k = 0; k < 8; k++) {
                const uint64_t df = add2(vp[k], negmu[bb][k]);
                q2 = fma2(mul2(df, df), invsv[bb][k], q2);
            }
            float ql, qh; upk2(q2, ql, qh);
            g_x[((size_t)(b0 + bb) * NIc + i0 + ii) * NOc + j] = fmaf(-0.5f, ql + qh, sL[bb]);
        }
    }
}

// ============================================================================
// K2: row softmax stats. Warp per (b,i) row of 128 logits: M = max, then
// writes (M, act/T) where T = sum exp(x-M). 8 warps / 256-thread block.
// ============================================================================
__global__ __launch_bounds__(256) void rowmt_kernel(const float* __restrict__ act)
{
    const int row  = (blockIdx.x << 3) + (threadIdx.x >> 5);  // 0..65535
    const int lane = threadIdx.x & 31;
    const float* xr = g_x + (size_t)row * NOc;

    const float x0 = xr[lane], x1 = xr[lane + 32], x2 = xr[lane + 64], x3 = xr[lane + 96];
    float m = fmaxf(fmaxf(x0, x1), fmaxf(x2, x3));
    #pragma unroll
    for (int off = 16; off; off >>= 1)
        m = fmaxf(m, __shfl_xor_sync(0xffffffffu, m, off));
    float s = __expf(x0 - m) + __expf(x1 - m) + __expf(x2 - m) + __expf(x3 - m);
    #pragma unroll
    for (int off = 16; off; off >>= 1)
        s += __shfl_xor_sync(0xffffffffu, s, off);
    if (lane == 0)
        g_rowMT[row] = make_float2(m, __fdividef(act[row], s));
}

// ============================================================================
// K3 / uniform pass: accumulate S0/S1/S2 partials. Block = 128 threads
// (j = tid), two b's, one i-tile. rp comes from act/NO (uniform) or from
// exp(x - M) * c (x streamed from g_x, (M,c) staged in smem). No barriers or
// shuffles in the loop.
// ============================================================================
template <bool UNIFORM>
__global__ __launch_bounds__(128) void accum_kernel(
    const float* __restrict__ pose, const float* __restrict__ act,
    const float* __restrict__ W)
{
    __shared__ uint64_t sPoseD[2][TIc][16];
    __shared__ float    sAct[2][TIc];     // uniform: act; else unused
    __shared__ float2   sMT[2][TIc];

    const int j    = threadIdx.x;
    const int tile = blockIdx.x;
    const int b0   = blockIdx.y << 1;
    const int i0   = tile * TIc;

    for (int idx = threadIdx.x; idx < 2 * TIc * 16; idx += 128) {
        const int bb = idx >> 10, rem = idx & 1023;
        const float f = pose[((size_t)(b0 + bb) * NIc + i0 + (rem >> 4)) * 16 + (rem & 15)];
        sPoseD[bb][rem >> 4][rem & 15] = pk2(f, f);
    }
    {
        const int bb = threadIdx.x >> 6, ii = threadIdx.x & 63;
        if (UNIFORM) sAct[bb][ii] = act[(b0 + bb) * NIc + i0 + ii];
        else         sMT[bb][ii]  = g_rowMT[(size_t)(b0 + bb) * NIc + i0 + ii];
    }
    __syncthreads();

    uint64_t S1[2][8], S2[2][8];
    float S0[2] = {0.f, 0.f};
    #pragma unroll
    for (int bb = 0; bb < 2; bb++)
        #pragma unroll
        for (int k = 0; k < 8; k++) { S1[bb][k] = 0ull; S2[bb][k] = 0ull; }

    #pragma unroll 1
    for (int ii = 0; ii < TIc; ii++) {
        uint64_t wpk[8];
        loadW8(W, i0 + ii, j, wpk);
        #pragma unroll
        for (int bb = 0; bb < 2; bb++) {
            uint64_t vp[8];
            votes8(wpk, sPoseD[bb][ii], vp);
            float rp;
            if (UNIFORM) {
                rp = sAct[bb][ii] * (1.f / NOc);
            } else {
                const float x = g_x[((size_t)(b0 + bb) * NIc + i0 + ii) * NOc + j];
                const float2 mt = sMT[bb][ii];
                rp = __expf(x - mt.x) * mt.y;
            }
            S0[bb] += rp;
            const uint64_t rpp = pk2(rp, rp);
            #pragma unroll
            for (int k = 0; k < 8; k++) {
                const uint64_t tmp = mul2(rpp, vp[k]);
                S1[bb][k] = add2(S1[bb][k], tmp);
                S2[bb][k] = fma2(tmp, vp[k], S2[bb][k]);
            }
        }
    }

    #pragma unroll
    for (int bb = 0; bb < 2; bb++) {
        float* pb = g_part + ((size_t)((b0 + bb) * NTc + tile) * NOc + j) * RW;
        pb[0] = S0[bb];
        #pragma unroll
        for (int k = 0; k < 8; k++) {
            *(uint64_t*)(pb + 4  + 2 * k) = S1[bb][k];
            *(uint64_t*)(pb + 20 + 2 * k) = S2[bb][k];
        }
    }
}

// ============================================================================
// Stats kernel: one warp per (b, j); lane = stat slot; coalesced tile loop,
// in-register reduce, shuffle-gather (undo (p,p+1) pair permutation), then
// mu / sigma2 / a_out (+ next-pass L & 1/sigma2 into g_statsT, or outputs).
// ============================================================================
template <bool FINAL>
__global__ __launch_bounds__(256) void stats_kernel(
    const float* __restrict__ beta_v,
    const float* __restrict__ beta_a,
    float lam,
    float* __restrict__ out)
{
    const int warp = (blockIdx.x * blockDim.x + threadIdx.x) >> 5;
    const int lane = threadIdx.x & 31;
    const int b = warp >> 7;
    const int j = warp & 127;

    const float* base = g_part + ((size_t)b * NTc * NOc + j) * RW;
    float acc = 0.f, acc2 = 0.f;
    #pragma unroll 4
    for (int tile = 0; tile < NTc; tile++) {
        const float* row = base + (size_t)tile * (NOc * RW);
        acc += row[lane];
        if (lane < 4) acc2 += row[32 + lane];
    }

    const int d  = lane & 15;
    const int q  = d & 3, pp = (d >> 3) & 1, h = (d >> 2) & 1;
    const int sl = 8 * pp + 2 * q + h;
    const float S0  = __shfl_sync(0xffffffffu, acc, 0);
    const float S1d = __shfl_sync(0xffffffffu, acc, 4 + sl);
    const float s2a = __shfl_sync(0xffffffffu, acc, (20 + sl) & 31);
    const float s2b = __shfl_sync(0xffffffffu, acc2, (sl >= 12) ? (sl - 12) : 0);
    const float S2d = (sl < 12) ? s2a : s2b;

    const float Rs = S0 + EPSf;
    const float invRs = 1.f / Rs;
    const float muv = S1d * invRs;
    const float srp = S2d - 2.f * muv * S1d + muv * muv * S0;  // exact expansion
    const float sig = srp * invRs + EPSf;
    const float lg  = logf(sig);
    float logsum = lg;
    #pragma unroll
    for (int off = 8; off; off >>= 1)
        logsum += __shfl_xor_sync(0xffffffffu, logsum, off);

    const float cost = (16.f * beta_v[j] + 0.5f * logsum) * Rs;
    const float aout = 1.f / (1.f + expf(-(lam * (beta_a[j] - cost))));

    if (FINAL) {
        if (lane < 16) out[(size_t)(b * NOc + j) * 16 + d] = muv;
        if (lane == 0) out[(size_t)Bn * NOc * 16 + b * NOc + j] = aout;
    } else {
        float* st = g_statsT + (size_t)b * 33 * NOc;
        if (lane < 16) {
            st[d * NOc + j]        = muv;
            st[(16 + d) * NOc + j] = 1.f / sig;
        }
        if (lane == 0)
            st[32 * NOc + j] = logf(aout + EPSf) - 0.5f * logsum - 8.f * LOG2PIf;
    }
}

extern "C" void kernel_launch(void* const* d_in, const int* in_sizes, int n_in,
                              void* d_out, int out_size) {
    const float* pose   = (const float*)d_in[0];
    const float* act    = (const float*)d_in[1];
    const float* W      = (const float*)d_in[2];
    const float* beta_v = (const float*)d_in[3];
    const float* beta_a = (const float*)d_in[4];
    float* out = (float*)d_out;

    dim3 gp(NTc, Bn / 2);                       // 32 x 16 blocks of 128
    const int rgrid = (Bn * NIc) / 8;           // 8192 blocks of 256 (warp/row)
    const int sgrid = (Bn * NOc * 32) / 256;    // 512 blocks of 256

    // t=0: uniform R
    accum_kernel<true><<<gp, 128>>>(pose, act, W);
    stats_kernel<false><<<sgrid, 256>>>(beta_v, beta_a, LAM1, out);
    // t=1
    logit_kernel<<<gp, 128>>>(pose, W);
    rowmt_kernel<<<rgrid, 256>>>(act);
    accum_kernel<false><<<gp, 128>>>(pose, act, W);
    stats_kernel<false><<<sgrid, 256>>>(beta_v, beta_a, LAM2, out);
    // t=2
    logit_kernel<<<gp, 128>>>(pose, W);
    rowmt_kernel<<<rgrid, 256>>>(act);
    accum_kernel<false><<<gp, 128>>>(pose, act, W);
    stats_kernel<true><<<sgrid, 256>>>(beta_v, beta_a, LAM3, out);
}

// round 8
// speedup vs baseline: 1.4764x; 1.1346x over previous
#include <cuda_runtime.h>
#include <math.h>
#include <stdint.h>

// Problem constants
#define Bn   32
#define NIc  2048
#define NOc  128
#define TIc  64              // i's per block in pass kernels
#define NTc  (NIc / TIc)     // 32 tiles
#define RW   36              // g_part row: [0]=S0, [4..19]=S1(permuted), [20..35]=S2(permuted)
#define EPSf 1e-9f
#define LOG2PIf 1.8378770664093453f

#define LAM1 0.0005f
#define LAM2 0.000975f
#define LAM3 0.00142625f

// Module-static scratch (allocation-free, deterministic)
__device__ __align__(16) float g_part[(size_t)Bn * NTc * NOc * RW];     // 18.9 MB
__device__ __align__(16) float g_statsT[(size_t)Bn * 33 * NOc];         // [b][s][j]
__device__ __align__(16) float g_x[(size_t)Bn * NIc * NOc];             // logits, 33.5 MB
__device__ __align__(16) float2 g_rowMT[(size_t)Bn * NIc];              // (M, a/T) per row
// Transposed+packed W: [i][k2][j] -> ulonglong2 = slots (2*k2, 2*k2+1)
// slot k=pp*4+r holds (W[i][j][2pp][r], W[i][j][2pp+1][r])
__device__ __align__(16) ulonglong2 g_Wt[(size_t)NIc * 4 * NOc];        // 16.8 MB

// ---------------- f32x2 packed helpers ----------------
static __device__ __forceinline__ uint64_t pk2(float lo, float hi) {
    uint64_t r; asm("mov.b64 %0, {%1, %2};" : "=l"(r) : "f"(lo), "f"(hi)); return r;
}
static __device__ __forceinline__ void upk2(uint64_t v, float& lo, float& hi) {
    asm("mov.b64 {%0, %1}, %2;" : "=f"(lo), "=f"(hi) : "l"(v));
}
static __device__ __forceinline__ uint64_t fma2(uint64_t a, uint64_t b, uint64_t c) {
    uint64_t d; asm("fma.rn.f32x2 %0, %1, %2, %3;" : "=l"(d) : "l"(a), "l"(b), "l"(c)); return d;
}
static __device__ __forceinline__ uint64_t mul2(uint64_t a, uint64_t b) {
    uint64_t d; asm("mul.rn.f32x2 %0, %1, %2;" : "=l"(d) : "l"(a), "l"(b)); return d;
}
static __device__ __forceinline__ uint64_t add2(uint64_t a, uint64_t b) {
    uint64_t d; asm("add.rn.f32x2 %0, %1, %2;" : "=l"(d) : "l"(a), "l"(b)); return d;
}

// votes: slot k=(pp*4+q) = (v[8pp+q], v[8pp+q+4]); wpk[pp*4+r]=(W[2pp][r],W[2pp+1][r]);
// pd[4r+q] = dup-packed pose (pose[r][q], pose[r][q])
static __device__ __forceinline__ void votes8(const uint64_t* __restrict__ wpk,
                                              const uint64_t* __restrict__ pd,
                                              uint64_t* __restrict__ vp) {
    #pragma unroll
    for (int k = 0; k < 8; k++) {
        const int pp = k >> 2, q = k & 3;
        uint64_t a = mul2(wpk[pp * 4 + 0], pd[0 + q]);
        a = fma2(wpk[pp * 4 + 1], pd[4 + q], a);
        a = fma2(wpk[pp * 4 + 2], pd[8 + q], a);
        vp[k] = fma2(wpk[pp * 4 + 3], pd[12 + q], a);
    }
}

// Coalesced packed-W load: 4x LDG.128, lane-consecutive 16B (nL=4)
static __device__ __forceinline__ void loadWt8(int i, int j, uint64_t* wpk) {
    const ulonglong2* wt = g_Wt + (size_t)i * 4 * NOc + j;
    const ulonglong2 a = wt[0], b = wt[NOc], c = wt[2 * NOc], d = wt[3 * NOc];
    wpk[0] = a.x; wpk[1] = a.y; wpk[2] = b.x; wpk[3] = b.y;
    wpk[4] = c.x; wpk[5] = c.y; wpk[6] = d.x; wpk[7] = d.y;
}

// ============================================================================
// W transpose+pack kernel (once per launch). Block=128 (j=tid), grid=NIc.
// ============================================================================
__global__ __launch_bounds__(128) void wt_kernel(const float* __restrict__ W) {
    const int i = blockIdx.x;
    const int j = threadIdx.x;
    const float4* wr = (const float4*)(W + ((size_t)i * NOc + j) * 16);
    const float4 w0 = wr[0], w1 = wr[1], w2 = wr[2], w3 = wr[3];
    ulonglong2* out = g_Wt + (size_t)i * 4 * NOc + j;
    out[0]        = make_ulonglong2(pk2(w0.x, w1.x), pk2(w0.y, w1.y));
    out[NOc]      = make_ulonglong2(pk2(w0.z, w1.z), pk2(w0.w, w1.w));
    out[2 * NOc]  = make_ulonglong2(pk2(w2.x, w3.x), pk2(w2.y, w3.y));
    out[3 * NOc]  = make_ulonglong2(pk2(w2.z, w3.z), pk2(w2.w, w3.w));
}

// ============================================================================
// K1: logit kernel. Block=128 (j=tid), two b's, one i-tile. Barrier-free loop.
// ============================================================================
__global__ __launch_bounds__(128) void logit_kernel(const float* __restrict__ pose)
{
    __shared__ uint64_t sPoseD[2][TIc][16];

    const int j    = threadIdx.x;
    const int tile = blockIdx.x;
    const int b0   = blockIdx.y << 1;
    const int i0   = tile * TIc;

    for (int idx = threadIdx.x; idx < 2 * TIc * 16; idx += 128) {
        const int bb = idx >> 10, rem = idx & 1023;
        const float f = pose[((size_t)(b0 + bb) * NIc + i0 + (rem >> 4)) * 16 + (rem & 15)];
        sPoseD[bb][rem >> 4][rem & 15] = pk2(f, f);
    }

    uint64_t negmu[2][8], invsv[2][8];
    float sL[2];
    #pragma unroll
    for (int bb = 0; bb < 2; bb++) {
        const float* st = g_statsT + (size_t)(b0 + bb) * 33 * NOc;
        float muv[16], iv[16];
        #pragma unroll
        for (int d = 0; d < 16; d++) {
            muv[d] = st[d * NOc + j];
            iv[d]  = st[(16 + d) * NOc + j];
        }
        sL[bb] = st[32 * NOc + j];
        #pragma unroll
        for (int k = 0; k < 8; k++) {
            const int pp = k >> 2, q = k & 3;
            negmu[bb][k] = pk2(-muv[8 * pp + q], -muv[8 * pp + q + 4]);
            invsv[bb][k] = pk2(iv[8 * pp + q], iv[8 * pp + q + 4]);
        }
    }
    __syncthreads();

    #pragma unroll 2
    for (int ii = 0; ii < TIc; ii++) {
        uint64_t wpk[8];
        loadWt8(i0 + ii, j, wpk);
        #pragma unroll
        for (int bb = 0; bb < 2; bb++) {
            uint64_t vp[8];
            votes8(wpk, sPoseD[bb][ii], vp);
            uint64_t q2a = 0ull, q2b = 0ull;   // split accumulators for ILP
            #pragma unroll
            for (int k = 0; k < 8; k += 2) {
                const uint64_t d0 = add2(vp[k],     negmu[bb][k]);
                const uint64_t d1 = add2(vp[k + 1], negmu[bb][k + 1]);
                q2a = fma2(mul2(d0, d0), invsv[bb][k],     q2a);
                q2b = fma2(mul2(d1, d1), invsv[bb][k + 1], q2b);
            }
            const uint64_t q2 = add2(q2a, q2b);
            float ql, qh; upk2(q2, ql, qh);
            g_x[((size_t)(b0 + bb) * NIc + i0 + ii) * NOc + j] = fmaf(-0.5f, ql + qh, sL[bb]);
        }
    }
}

// ============================================================================
// K2: row softmax stats. Warp per (b,i) row: writes (M, act/T).
// ============================================================================
__global__ __launch_bounds__(256) void rowmt_kernel(const float* __restrict__ act)
{
    const int row  = (blockIdx.x << 3) + (threadIdx.x >> 5);
    const int lane = threadIdx.x & 31;
    const float* xr = g_x + (size_t)row * NOc;

    const float x0 = xr[lane], x1 = xr[lane + 32], x2 = xr[lane + 64], x3 = xr[lane + 96];
    float m = fmaxf(fmaxf(x0, x1), fmaxf(x2, x3));
    #pragma unroll
    for (int off = 16; off; off >>= 1)
        m = fmaxf(m, __shfl_xor_sync(0xffffffffu, m, off));
    float s = __expf(x0 - m) + __expf(x1 - m) + __expf(x2 - m) + __expf(x3 - m);
    #pragma unroll
    for (int off = 16; off; off >>= 1)
        s += __shfl_xor_sync(0xffffffffu, s, off);
    if (lane == 0)
        g_rowMT[row] = make_float2(m, __fdividef(act[row], s));
}

// ============================================================================
// K3 / uniform pass: accumulate S0/S1/S2 partials. Barrier-free loop.
// ============================================================================
template <bool UNIFORM>
__global__ __launch_bounds__(128) void accum_kernel(
    const float* __restrict__ pose, const float* __restrict__ act)
{
    __shared__ uint64_t sPoseD[2][TIc][16];
    __shared__ float    sAct[2][TIc];
    __shared__ float2   sMT[2][TIc];

    const int j    = threadIdx.x;
    const int tile = blockIdx.x;
    const int b0   = blockIdx.y << 1;
    const int i0   = tile * TIc;

    for (int idx = threadIdx.x; idx < 2 * TIc * 16; idx += 128) {
        const int bb = idx >> 10, rem = idx & 1023;
        const float f = pose[((size_t)(b0 + bb) * NIc + i0 + (rem >> 4)) * 16 + (rem & 15)];
        sPoseD[bb][rem >> 4][rem & 15] = pk2(f, f);
    }
    {
        const int bb = threadIdx.x >> 6, ii = threadIdx.x & 63;
        if (UNIFORM) sAct[bb][ii] = act[(b0 + bb) * NIc + i0 + ii];
        else         sMT[bb][ii]  = g_rowMT[(size_t)(b0 + bb) * NIc + i0 + ii];
    }
    __syncthreads();

    uint64_t S1[2][8], S2[2][8];
    float S0[2] = {0.f, 0.f};
    #pragma unroll
    for (int bb = 0; bb < 2; bb++)
        #pragma unroll
        for (int k = 0; k < 8; k++) { S1[bb][k] = 0ull; S2[bb][k] = 0ull; }

    #pragma unroll 2
    for (int ii = 0; ii < TIc; ii++) {
        uint64_t wpk[8];
        loadWt8(i0 + ii, j, wpk);

        // issue the (latency-bound) x loads BEFORE the vote math so they
        // retire under the FMA shadow
        float xv[2];
        if (!UNIFORM) {
            #pragma unroll
            for (int bb = 0; bb < 2; bb++)
                xv[bb] = g_x[((size_t)(b0 + bb) * NIc + i0 + ii) * NOc + j];
        }

        #pragma unroll
        for (int bb = 0; bb < 2; bb++) {
            uint64_t vp[8];
            votes8(wpk, sPoseD[bb][ii], vp);
            float rp;
            if (UNIFORM) {
                rp = sAct[bb][ii] * (1.f / NOc);
            } else {
                const float2 mt = sMT[bb][ii];
                rp = __expf(xv[bb] - mt.x) * mt.y;
            }
            S0[bb] += rp;
            const uint64_t rpp = pk2(rp, rp);
            #pragma unroll
            for (int k = 0; k < 8; k++) {
                const uint64_t tmp = mul2(rpp, vp[k]);
                S1[bb][k] = add2(S1[bb][k], tmp);
                S2[bb][k] = fma2(tmp, vp[k], S2[bb][k]);
            }
        }
    }

    #pragma unroll
    for (int bb = 0; bb < 2; bb++) {
        float* pb = g_part + ((size_t)((b0 + bb) * NTc + tile) * NOc + j) * RW;
        pb[0] = S0[bb];
        #pragma unroll
        for (int k = 0; k < 8; k++) {
            *(uint64_t*)(pb + 4  + 2 * k) = S1[bb][k];
            *(uint64_t*)(pb + 20 + 2 * k) = S2[bb][k];
        }
    }
}

// ============================================================================
// Stats kernel: one warp per (b, j); lane = stat slot; coalesced tile loop.
// ============================================================================
template <bool FINAL>
__global__ __launch_bounds__(256) void stats_kernel(
    const float* __restrict__ beta_v,
    const float* __restrict__ beta_a,
    float lam,
    float* __restrict__ out)
{
    const int warp = (blockIdx.x * blockDim.x + threadIdx.x) >> 5;
    const int lane = threadIdx.x & 31;
    const int b = warp >> 7;
    const int j = warp & 127;

    const float* base = g_part + ((size_t)b * NTc * NOc + j) * RW;
    float acc = 0.f, acc2 = 0.f;
    #pragma unroll 4
    for (int tile = 0; tile < NTc; tile++) {
        const float* row = base + (size_t)tile * (NOc * RW);
        acc += row[lane];
        if (lane < 4) acc2 += row[32 + lane];
    }

    const int d  = lane & 15;
    const int q  = d & 3, pp = (d >> 3) & 1, h = (d >> 2) & 1;
    const int sl = 8 * pp + 2 * q + h;
    const float S0  = __shfl_sync(0xffffffffu, acc, 0);
    const float S1d = __shfl_sync(0xffffffffu, acc, 4 + sl);
    const float s2a = __shfl_sync(0xffffffffu, acc, (20 + sl) & 31);
    const float s2b = __shfl_sync(0xffffffffu, acc2, (sl >= 12) ? (sl - 12) : 0);
    const float S2d = (sl < 12) ? s2a : s2b;

    const float Rs = S0 + EPSf;
    const float invRs = 1.f / Rs;
    const float muv = S1d * invRs;
    const float srp = S2d - 2.f * muv * S1d + muv * muv * S0;
    const float sig = srp * invRs + EPSf;
    const float lg  = logf(sig);
    float logsum = lg;
    #pragma unroll
    for (int off = 8; off; off >>= 1)
        logsum += __shfl_xor_sync(0xffffffffu, logsum, off);

    const float cost = (16.f * beta_v[j] + 0.5f * logsum) * Rs;
    const float aout = 1.f / (1.f + expf(-(lam * (beta_a[j] - cost))));

    if (FINAL) {
        if (lane < 16) out[(size_t)(b * NOc + j) * 16 + d] = muv;
        if (lane == 0) out[(size_t)Bn * NOc * 16 + b * NOc + j] = aout;
    } else {
        float* st = g_statsT + (size_t)b * 33 * NOc;
        if (lane < 16) {
            st[d * NOc + j]        = muv;
            st[(16 + d) * NOc + j] = 1.f / sig;
        }
        if (lane == 0)
            st[32 * NOc + j] = logf(aout + EPSf) - 0.5f * logsum - 8.f * LOG2PIf;
    }
}

extern "C" void kernel_launch(void* const* d_in, const int* in_sizes, int n_in,
                              void* d_out, int out_size) {
    const float* pose   = (const float*)d_in[0];
    const float* act    = (const float*)d_in[1];
    const float* W      = (const float*)d_in[2];
    const float* beta_v = (const float*)d_in[3];
    const float* beta_a = (const float*)d_in[4];
    float* out = (float*)d_out;

    dim3 gp(NTc, Bn / 2);                       // 32 x 16 blocks of 128
    const int rgrid = (Bn * NIc) / 8;           // 8192 blocks of 256 (warp/row)
    const int sgrid = (Bn * NOc * 32) / 256;    // 512 blocks of 256

    wt_kernel<<<NIc, 128>>>(W);                 // pack+transpose W once

    // t=0: uniform R
    accum_kernel<true><<<gp, 128>>>(pose, act);
    stats_kernel<false><<<sgrid, 256>>>(beta_v, beta_a, LAM1, out);
    // t=1
    logit_kernel<<<gp, 128>>>(pose);
    rowmt_kernel<<<rgrid, 256>>>(act);
    accum_kernel<false><<<gp, 128>>>(pose, act);
    stats_kernel<false><<<sgrid, 256>>>(beta_v, beta_a, LAM2, out);
    // t=2
    logit_kernel<<<gp, 128>>>(pose);
    rowmt_kernel<<<rgrid, 256>>>(act);
    accum_kernel<false><<<gp, 128>>>(pose, act);
    stats_kernel<true><<<sgrid, 256>>>(beta_v, beta_a, LAM3, out);
}